// round 8
// baseline (speedup 1.0000x reference)
#include <cuda_runtime.h>

// VectorQuantize, register-tiled fp32. B x 64 rows vs 512 x 64 codebook.
// R8: MT=192, thread tile 6 rows x 4 codes (acc 48 regs) + explicit
// double-buffered dp pipeline -> no spills, LDS latency hidden.
// Rows per thread are strided (2ty, 2ty+1, +64, +128) so every z LDS.128
// has a 32B warp span (1 wavefront).
//
// Precision contract (validated R1/R3/R4/R7, rel_err == 0.0): fp32
// throughout, dist = fl(fl(z_sq - 2*dot) + c_sq); dot = single f32x2 chain
// over dp ascending then fl(x+y); z_sq 4-chain stride-4; c_sq sequential
// scalar; argmin strict '<' ascending k in-thread, lexicographic (dist,k)
// across threads -> first-index tie break (jnp.argmin).

#define VQ_K     512
#define VQ_D     64
#define VQ_TPB   512
#define VQ_MT    192        // rows per CTA
#define VQ_RT    6          // rows per thread (strided)
#define VQ_KT    4          // codes per thread per sweep
#define VQ_SC    512        // cT2 dp-row stride (ull)
#define VQ_SZ    192        // zT2 dp-row stride (ull)
#define VQ_NIT   8          // k-sweeps (64 codes per sweep)

typedef unsigned long long ull;

__device__ __forceinline__ ull vq_fma2(ull a, ull b, ull c) {
    ull d;
    asm("fma.rn.f32x2 %0, %1, %2, %3;" : "=l"(d) : "l"(a), "l"(b), "l"(c));
    return d;
}
__device__ __forceinline__ ull vq_add2(ull a, ull b) {
    ull d;
    asm("add.rn.f32x2 %0, %1, %2;" : "=l"(d) : "l"(a), "l"(b));
    return d;
}
__device__ __forceinline__ float2 vq_unpack(ull a) {
    float2 f;
    asm("mov.b64 {%0, %1}, %2;" : "=f"(f.x), "=f"(f.y) : "l"(a));
    return f;
}
__device__ __forceinline__ ull vq_pack(float x, float y) {
    ull d;
    asm("mov.b64 %0, {%1, %2};" : "=l"(d) : "f"(x), "f"(y));
    return d;
}

#define VQ_CT2_ULL (32 * VQ_SC)      // 16384 ull = 131072 B
#define VQ_ZT2_ULL (32 * VQ_SZ)      //  6144 ull =  49152 B
// cT2 + zT2 + csq(512f) + zsq(192f) = 183040 B
#define VQ_SMEM_BYTES ((VQ_CT2_ULL + VQ_ZT2_ULL) * 8 + (VQ_K + VQ_MT) * 4)
// reduction overlay on zT2: 192*17*(4+4) = 26112 B < 49152 B

__global__ void __launch_bounds__(VQ_TPB, 1)
vq_kernel(const float* __restrict__ z, const float* __restrict__ cb,
          float* __restrict__ out, int B) {
    extern __shared__ ull sm[];
    ull*   cT2   = sm;                           // [dp*512 + k]
    ull*   zT2   = sm + VQ_CT2_ULL;              // [dp*192 + r]
    float* s_csq = (float*)(zT2 + VQ_ZT2_ULL);   // [512]
    float* s_zsq = s_csq + VQ_K;                 // [192]
    float* s_rd  = (float*)zT2;                  // overlay [192*17]
    int*   s_rk  = (int*)(s_rd + VQ_MT * 17);    // overlay [192*17]

    const int tid = threadIdx.x;
    const long long base = (long long)blockIdx.x * VQ_MT;
    const int rows_in = (int)((B - base) < VQ_MT ? (B - base) : VQ_MT);

    // ---- stage codebook transposed, k-minor (conflict-free STS) ----
    {
        const float4* cb4 = reinterpret_cast<const float4*>(cb);
        #pragma unroll 4
        for (int i = tid; i < VQ_K * 16; i += VQ_TPB) {
            int k = i & 511, dg = i >> 9;
            float4 v = cb4[k * 16 + dg];
            cT2[(2 * dg)     * VQ_SC + k] = vq_pack(v.x, v.y);
            cT2[(2 * dg + 1) * VQ_SC + k] = vq_pack(v.z, v.w);
        }
    }
    // ---- stage z tile transposed, r-minor (conflict-free STS) ----
    {
        const float4* z4 = reinterpret_cast<const float4*>(z + base * VQ_D);
        #pragma unroll 2
        for (int i = tid; i < VQ_MT * 16; i += VQ_TPB) {
            int dg = i / VQ_MT, r = i - dg * VQ_MT;
            float4 v = (r < rows_in) ? z4[r * 16 + dg]
                                     : make_float4(0.f, 0.f, 0.f, 0.f);
            zT2[(2 * dg)     * VQ_SZ + r] = vq_pack(v.x, v.y);
            zT2[(2 * dg + 1) * VQ_SZ + r] = vq_pack(v.z, v.w);
        }
    }
    __syncthreads();

    // ---- c_sq: sequential scalar over d ascending (chain == R1..R7) ----
    {
        int k = tid;   // TPB == 512 == VQ_K
        float s = 0.0f;
        #pragma unroll
        for (int dp = 0; dp < 32; ++dp) {
            float2 c = vq_unpack(cT2[dp * VQ_SC + k]);
            s = __fmaf_rn(c.x, c.x, s);
            s = __fmaf_rn(c.y, c.y, s);
        }
        s_csq[k] = s;
    }
    // ---- z_sq: 4-chain pairwise, stride-4 interleave (chain == R1..R7) ----
    if (tid < VQ_MT) {
        int r = tid;
        ull a0 = 0, a1 = 0, a2 = 0, a3 = 0;
        #pragma unroll
        for (int i = 0; i < 32; i += 4) {
            ull p0 = zT2[(i + 0) * VQ_SZ + r];
            ull p1 = zT2[(i + 1) * VQ_SZ + r];
            ull p2 = zT2[(i + 2) * VQ_SZ + r];
            ull p3 = zT2[(i + 3) * VQ_SZ + r];
            a0 = vq_fma2(p0, p0, a0);
            a1 = vq_fma2(p1, p1, a1);
            a2 = vq_fma2(p2, p2, a2);
            a3 = vq_fma2(p3, p3, a3);
        }
        float2 s = vq_unpack(vq_add2(vq_add2(a0, a1), vq_add2(a2, a3)));
        s_zsq[r] = __fadd_rn(s.x, s.y);
    }
    __syncthreads();

    // ---- main loop: 8 k-sweeps, thread tile 6 strided rows x 4 codes ----
    const int tx = tid & 15, ty = tid >> 4;      // tx [0,16), ty [0,32)
    const int r0 = 2 * ty;                       // rows r0+{0,1}, +64, +128

    float best[VQ_RT];
    int   bk[VQ_RT];
    #pragma unroll
    for (int r = 0; r < VQ_RT; ++r) { best[r] = __int_as_float(0x7f800000); bk[r] = 0; }

    #pragma unroll 1
    for (int it = 0; it < VQ_NIT; ++it) {
        const int K0 = it * 64;
        const int kA = K0 + 2 * tx;              // codes kA, kA+1
        const int kB = kA + 32;                  // codes kB, kB+1

        ull acc[VQ_RT][VQ_KT];
        #pragma unroll
        for (int r = 0; r < VQ_RT; ++r)
            #pragma unroll
            for (int kk = 0; kk < VQ_KT; ++kk) acc[r][kk] = 0;

        const ull* cp = cT2 + kA;
        const ull* zp = zT2 + r0;

        // prefetch dp = 0
        ulonglong2 cA0 = *reinterpret_cast<const ulonglong2*>(cp);
        ulonglong2 cB0 = *reinterpret_cast<const ulonglong2*>(cp + 32);
        ulonglong2 za0 = *reinterpret_cast<const ulonglong2*>(zp);
        ulonglong2 zb0 = *reinterpret_cast<const ulonglong2*>(zp + 64);
        ulonglong2 zc0 = *reinterpret_cast<const ulonglong2*>(zp + 128);

        #pragma unroll
        for (int dp = 0; dp < 32; dp += 2) {
            // prefetch dp+1 into buffer 1
            ulonglong2 cA1 = *reinterpret_cast<const ulonglong2*>(cp + (dp + 1) * VQ_SC);
            ulonglong2 cB1 = *reinterpret_cast<const ulonglong2*>(cp + (dp + 1) * VQ_SC + 32);
            ulonglong2 za1 = *reinterpret_cast<const ulonglong2*>(zp + (dp + 1) * VQ_SZ);
            ulonglong2 zb1 = *reinterpret_cast<const ulonglong2*>(zp + (dp + 1) * VQ_SZ + 64);
            ulonglong2 zc1 = *reinterpret_cast<const ulonglong2*>(zp + (dp + 1) * VQ_SZ + 128);

            // FMA block for dp (buffer 0)
            {
                ull cf[VQ_KT] = { cA0.x, cA0.y, cB0.x, cB0.y };
                ull zr[VQ_RT] = { za0.x, za0.y, zb0.x, zb0.y, zc0.x, zc0.y };
                #pragma unroll
                for (int r = 0; r < VQ_RT; ++r)
                    #pragma unroll
                    for (int kk = 0; kk < VQ_KT; ++kk)
                        acc[r][kk] = vq_fma2(zr[r], cf[kk], acc[r][kk]);
            }

            // prefetch dp+2 into buffer 0 (compile-time guard; loop unrolled)
            if (dp + 2 < 32) {
                cA0 = *reinterpret_cast<const ulonglong2*>(cp + (dp + 2) * VQ_SC);
                cB0 = *reinterpret_cast<const ulonglong2*>(cp + (dp + 2) * VQ_SC + 32);
                za0 = *reinterpret_cast<const ulonglong2*>(zp + (dp + 2) * VQ_SZ);
                zb0 = *reinterpret_cast<const ulonglong2*>(zp + (dp + 2) * VQ_SZ + 64);
                zc0 = *reinterpret_cast<const ulonglong2*>(zp + (dp + 2) * VQ_SZ + 128);
            }

            // FMA block for dp+1 (buffer 1)
            {
                ull cf[VQ_KT] = { cA1.x, cA1.y, cB1.x, cB1.y };
                ull zr[VQ_RT] = { za1.x, za1.y, zb1.x, zb1.y, zc1.x, zc1.y };
                #pragma unroll
                for (int r = 0; r < VQ_RT; ++r)
                    #pragma unroll
                    for (int kk = 0; kk < VQ_KT; ++kk)
                        acc[r][kk] = vq_fma2(zr[r], cf[kk], acc[r][kk]);
            }
        }

        // per-sweep epilogue: dist + argmin (k ascending within thread)
        const int kidx[VQ_KT] = { kA, kA + 1, kB, kB + 1 };
        #pragma unroll
        for (int j = 0; j < 3; ++j) {
            #pragma unroll
            for (int h = 0; h < 2; ++h) {
                const int r = 2 * j + h;
                const float zq = s_zsq[r0 + 64 * j + h];
                #pragma unroll
                for (int kk = 0; kk < VQ_KT; ++kk) {
                    float2 f = vq_unpack(acc[r][kk]);
                    float dot  = __fadd_rn(f.x, f.y);
                    float t    = __fsub_rn(zq, __fmul_rn(2.0f, dot));
                    float dist = __fadd_rn(t, s_csq[kidx[kk]]);
                    bool p = dist < best[r];
                    best[r] = p ? dist : best[r];
                    bk[r]   = p ? kidx[kk] : bk[r];
                }
            }
        }
    }

    // ---- cross-thread argmin reduction (overlay on dead zT2) ----
    __syncthreads();   // all main-loop zT2 reads complete
    #pragma unroll
    for (int j = 0; j < 3; ++j)
        #pragma unroll
        for (int h = 0; h < 2; ++h) {
            const int row = r0 + 64 * j + h;
            s_rd[row * 17 + tx] = best[2 * j + h];
            s_rk[row * 17 + tx] = bk[2 * j + h];
        }
    __syncthreads();
    if (tid < VQ_MT) {
        int r = tid;
        float bd = s_rd[r * 17 + 0];
        int   bi = s_rk[r * 17 + 0];
        #pragma unroll
        for (int t = 1; t < 16; ++t) {
            float d = s_rd[r * 17 + t];
            int   i = s_rk[r * 17 + t];
            bool p = (d < bd) || (d == bd && i < bi);
            bd = p ? d : bd;
            bi = p ? i : bi;
        }
        s_rk[r * 17] = bi;
    }
    __syncthreads();

    // ---- outputs: z and cb from GLOBAL (coalesced; L2-resident) ----
    {
        const float4* cb4 = reinterpret_cast<const float4*>(cb);
        const float4* z4  = reinterpret_cast<const float4*>(z + base * VQ_D);
        float4* o1 = reinterpret_cast<float4*>(out) + base * 16;
        float4* o2 = reinterpret_cast<float4*>(out) + (long long)B * 16 + base * 16;
        #pragma unroll 2
        for (int c = tid; c < VQ_MT * 16; c += VQ_TPB) {
            int r = c >> 4, dg = c & 15;
            if (r >= rows_in) break;
            int kbest = s_rk[r * 17];
            float4 qv = cb4[kbest * 16 + dg];
            float4 zv = z4[c];
            float4 w;
            w.x = __fadd_rn(zv.x, __fsub_rn(qv.x, zv.x));
            w.y = __fadd_rn(zv.y, __fsub_rn(qv.y, zv.y));
            w.z = __fadd_rn(zv.z, __fsub_rn(qv.z, zv.z));
            w.w = __fadd_rn(zv.w, __fsub_rn(qv.w, zv.w));
            o1[c] = w;
            o2[c] = qv;
        }
    }
}

extern "C" void kernel_launch(void* const* d_in, const int* in_sizes, int n_in,
                              void* d_out, int out_size) {
    const float* z  = (const float*)d_in[0];
    const float* cb = (const float*)d_in[1];
    int sz0 = in_sizes[0];
    int sz1 = (n_in > 1) ? in_sizes[1] : 0;
    if (sz0 < sz1) {   // codebook is the small input (K*D = 32768)
        const float* t = z; z = cb; cb = t;
        int ts = sz0; sz0 = sz1; sz1 = ts;
    }
    int B = sz0 / VQ_D;

    cudaFuncSetAttribute(vq_kernel, cudaFuncAttributeMaxDynamicSharedMemorySize,
                         VQ_SMEM_BYTES);
    int grid = (B + VQ_MT - 1) / VQ_MT;
    vq_kernel<<<grid, VQ_TPB, VQ_SMEM_BYTES>>>(z, cb, (float*)d_out, B);
}

// round 9
// speedup vs baseline: 3.9322x; 3.9322x over previous
#include <cuda_runtime.h>

// VectorQuantize, register-tiled fp32. B x 64 rows vs 512 x 64 codebook.
// R9 = R8 WITHOUT the manual double-buffer (it spilled acc under the 128-reg
// cap -> 4x regression). Simple compiler-scheduled dp loop, 6x4 thread tile
// (acc 48 regs) leaves ~25 regs headroom for ptxas's own load hoisting.
// Strided rows (2ty, 2ty+1, +64, +128): every z LDS.128 spans 32B -> 1 wf.
//
// Precision contract (validated R1/R3/R4/R7/R8, rel_err == 0.0): fp32
// throughout, dist = fl(fl(z_sq - 2*dot) + c_sq); dot = single f32x2 chain
// over dp ascending then fl(x+y); z_sq 4-chain stride-4; c_sq sequential
// scalar; argmin strict '<' ascending k in-thread, lexicographic (dist,k)
// across threads -> first-index tie break (jnp.argmin).

#define VQ_K     512
#define VQ_D     64
#define VQ_TPB   512
#define VQ_MT    192        // rows per CTA
#define VQ_RT    6          // rows per thread (strided)
#define VQ_KT    4          // codes per thread per sweep
#define VQ_SC    512        // cT2 dp-row stride (ull)
#define VQ_SZ    192        // zT2 dp-row stride (ull)
#define VQ_NIT   8          // k-sweeps (64 codes per sweep)

typedef unsigned long long ull;

__device__ __forceinline__ ull vq_fma2(ull a, ull b, ull c) {
    ull d;
    asm("fma.rn.f32x2 %0, %1, %2, %3;" : "=l"(d) : "l"(a), "l"(b), "l"(c));
    return d;
}
__device__ __forceinline__ ull vq_add2(ull a, ull b) {
    ull d;
    asm("add.rn.f32x2 %0, %1, %2;" : "=l"(d) : "l"(a), "l"(b));
    return d;
}
__device__ __forceinline__ float2 vq_unpack(ull a) {
    float2 f;
    asm("mov.b64 {%0, %1}, %2;" : "=f"(f.x), "=f"(f.y) : "l"(a));
    return f;
}
__device__ __forceinline__ ull vq_pack(float x, float y) {
    ull d;
    asm("mov.b64 %0, {%1, %2};" : "=l"(d) : "f"(x), "f"(y));
    return d;
}

#define VQ_CT2_ULL (32 * VQ_SC)      // 16384 ull = 131072 B
#define VQ_ZT2_ULL (32 * VQ_SZ)      //  6144 ull =  49152 B
// cT2 + zT2 + csq(512f) + zsq(192f) = 183040 B
#define VQ_SMEM_BYTES ((VQ_CT2_ULL + VQ_ZT2_ULL) * 8 + (VQ_K + VQ_MT) * 4)
// reduction overlay on zT2: 192*17*(4+4) = 26112 B < 49152 B

__global__ void __launch_bounds__(VQ_TPB, 1)
vq_kernel(const float* __restrict__ z, const float* __restrict__ cb,
          float* __restrict__ out, int B) {
    extern __shared__ ull sm[];
    ull*   cT2   = sm;                           // [dp*512 + k]
    ull*   zT2   = sm + VQ_CT2_ULL;              // [dp*192 + r]
    float* s_csq = (float*)(zT2 + VQ_ZT2_ULL);   // [512]
    float* s_zsq = s_csq + VQ_K;                 // [192]
    float* s_rd  = (float*)zT2;                  // overlay [192*17]
    int*   s_rk  = (int*)(s_rd + VQ_MT * 17);    // overlay [192*17]

    const int tid = threadIdx.x;
    const long long base = (long long)blockIdx.x * VQ_MT;
    const int rows_in = (int)((B - base) < VQ_MT ? (B - base) : VQ_MT);

    // ---- stage codebook transposed, k-minor (conflict-free STS) ----
    {
        const float4* cb4 = reinterpret_cast<const float4*>(cb);
        #pragma unroll 4
        for (int i = tid; i < VQ_K * 16; i += VQ_TPB) {
            int k = i & 511, dg = i >> 9;
            float4 v = cb4[k * 16 + dg];
            cT2[(2 * dg)     * VQ_SC + k] = vq_pack(v.x, v.y);
            cT2[(2 * dg + 1) * VQ_SC + k] = vq_pack(v.z, v.w);
        }
    }
    // ---- stage z tile transposed, r-minor (conflict-free STS) ----
    {
        const float4* z4 = reinterpret_cast<const float4*>(z + base * VQ_D);
        #pragma unroll 2
        for (int i = tid; i < VQ_MT * 16; i += VQ_TPB) {
            int dg = i / VQ_MT, r = i - dg * VQ_MT;
            float4 v = (r < rows_in) ? z4[r * 16 + dg]
                                     : make_float4(0.f, 0.f, 0.f, 0.f);
            zT2[(2 * dg)     * VQ_SZ + r] = vq_pack(v.x, v.y);
            zT2[(2 * dg + 1) * VQ_SZ + r] = vq_pack(v.z, v.w);
        }
    }
    __syncthreads();

    // ---- c_sq: sequential scalar over d ascending (chain == R1..R8) ----
    {
        int k = tid;   // TPB == 512 == VQ_K
        float s = 0.0f;
        #pragma unroll
        for (int dp = 0; dp < 32; ++dp) {
            float2 c = vq_unpack(cT2[dp * VQ_SC + k]);
            s = __fmaf_rn(c.x, c.x, s);
            s = __fmaf_rn(c.y, c.y, s);
        }
        s_csq[k] = s;
    }
    // ---- z_sq: 4-chain pairwise, stride-4 interleave (chain == R1..R8) ----
    if (tid < VQ_MT) {
        int r = tid;
        ull a0 = 0, a1 = 0, a2 = 0, a3 = 0;
        #pragma unroll
        for (int i = 0; i < 32; i += 4) {
            ull p0 = zT2[(i + 0) * VQ_SZ + r];
            ull p1 = zT2[(i + 1) * VQ_SZ + r];
            ull p2 = zT2[(i + 2) * VQ_SZ + r];
            ull p3 = zT2[(i + 3) * VQ_SZ + r];
            a0 = vq_fma2(p0, p0, a0);
            a1 = vq_fma2(p1, p1, a1);
            a2 = vq_fma2(p2, p2, a2);
            a3 = vq_fma2(p3, p3, a3);
        }
        float2 s = vq_unpack(vq_add2(vq_add2(a0, a1), vq_add2(a2, a3)));
        s_zsq[r] = __fadd_rn(s.x, s.y);
    }
    __syncthreads();

    // ---- main loop: 8 k-sweeps, thread tile 6 strided rows x 4 codes ----
    const int tx = tid & 15, ty = tid >> 4;      // tx [0,16), ty [0,32)
    const int r0 = 2 * ty;                       // rows r0+{0,1}, +64, +128

    float best[VQ_RT];
    int   bk[VQ_RT];
    #pragma unroll
    for (int r = 0; r < VQ_RT; ++r) { best[r] = __int_as_float(0x7f800000); bk[r] = 0; }

    #pragma unroll 1
    for (int it = 0; it < VQ_NIT; ++it) {
        const int K0 = it * 64;
        const int kA = K0 + 2 * tx;              // codes kA, kA+1
        const int kB = kA + 32;                  // codes kB, kB+1

        ull acc[VQ_RT][VQ_KT];
        #pragma unroll
        for (int r = 0; r < VQ_RT; ++r)
            #pragma unroll
            for (int kk = 0; kk < VQ_KT; ++kk) acc[r][kk] = 0;

        const ull* cp = cT2 + kA;
        const ull* zp = zT2 + r0;

        #pragma unroll 4
        for (int dp = 0; dp < 32; ++dp) {
            ulonglong2 cA = *reinterpret_cast<const ulonglong2*>(cp + dp * VQ_SC);
            ulonglong2 cB = *reinterpret_cast<const ulonglong2*>(cp + dp * VQ_SC + 32);
            ull cf[VQ_KT] = { cA.x, cA.y, cB.x, cB.y };

            ulonglong2 za = *reinterpret_cast<const ulonglong2*>(zp + dp * VQ_SZ);
            ulonglong2 zb = *reinterpret_cast<const ulonglong2*>(zp + dp * VQ_SZ + 64);
            ulonglong2 zc = *reinterpret_cast<const ulonglong2*>(zp + dp * VQ_SZ + 128);
            ull zr[VQ_RT] = { za.x, za.y, zb.x, zb.y, zc.x, zc.y };

            #pragma unroll
            for (int r = 0; r < VQ_RT; ++r)
                #pragma unroll
                for (int kk = 0; kk < VQ_KT; ++kk)
                    acc[r][kk] = vq_fma2(zr[r], cf[kk], acc[r][kk]);
        }

        // per-sweep epilogue: dist + argmin (k ascending within thread)
        const int kidx[VQ_KT] = { kA, kA + 1, kB, kB + 1 };
        #pragma unroll
        for (int j = 0; j < 3; ++j) {
            #pragma unroll
            for (int h = 0; h < 2; ++h) {
                const int r = 2 * j + h;
                const float zq = s_zsq[r0 + 64 * j + h];
                #pragma unroll
                for (int kk = 0; kk < VQ_KT; ++kk) {
                    float2 f = vq_unpack(acc[r][kk]);
                    float dot  = __fadd_rn(f.x, f.y);
                    float t    = __fsub_rn(zq, __fmul_rn(2.0f, dot));
                    float dist = __fadd_rn(t, s_csq[kidx[kk]]);
                    bool p = dist < best[r];
                    best[r] = p ? dist : best[r];
                    bk[r]   = p ? kidx[kk] : bk[r];
                }
            }
        }
    }

    // ---- cross-thread argmin reduction (overlay on dead zT2) ----
    __syncthreads();   // all main-loop zT2 reads complete
    #pragma unroll
    for (int j = 0; j < 3; ++j)
        #pragma unroll
        for (int h = 0; h < 2; ++h) {
            const int row = r0 + 64 * j + h;
            s_rd[row * 17 + tx] = best[2 * j + h];
            s_rk[row * 17 + tx] = bk[2 * j + h];
        }
    __syncthreads();
    if (tid < VQ_MT) {
        int r = tid;
        float bd = s_rd[r * 17 + 0];
        int   bi = s_rk[r * 17 + 0];
        #pragma unroll
        for (int t = 1; t < 16; ++t) {
            float d = s_rd[r * 17 + t];
            int   i = s_rk[r * 17 + t];
            bool p = (d < bd) || (d == bd && i < bi);
            bd = p ? d : bd;
            bi = p ? i : bi;
        }
        s_rk[r * 17] = bi;
    }
    __syncthreads();

    // ---- outputs: z and cb from GLOBAL (coalesced; L2-resident) ----
    {
        const float4* cb4 = reinterpret_cast<const float4*>(cb);
        const float4* z4  = reinterpret_cast<const float4*>(z + base * VQ_D);
        float4* o1 = reinterpret_cast<float4*>(out) + base * 16;
        float4* o2 = reinterpret_cast<float4*>(out) + (long long)B * 16 + base * 16;
        #pragma unroll 2
        for (int c = tid; c < VQ_MT * 16; c += VQ_TPB) {
            int r = c >> 4, dg = c & 15;
            if (r >= rows_in) break;
            int kbest = s_rk[r * 17];
            float4 qv = cb4[kbest * 16 + dg];
            float4 zv = z4[c];
            float4 w;
            w.x = __fadd_rn(zv.x, __fsub_rn(qv.x, zv.x));
            w.y = __fadd_rn(zv.y, __fsub_rn(qv.y, zv.y));
            w.z = __fadd_rn(zv.z, __fsub_rn(qv.z, zv.z));
            w.w = __fadd_rn(zv.w, __fsub_rn(qv.w, zv.w));
            o1[c] = w;
            o2[c] = qv;
        }
    }
}

extern "C" void kernel_launch(void* const* d_in, const int* in_sizes, int n_in,
                              void* d_out, int out_size) {
    const float* z  = (const float*)d_in[0];
    const float* cb = (const float*)d_in[1];
    int sz0 = in_sizes[0];
    int sz1 = (n_in > 1) ? in_sizes[1] : 0;
    if (sz0 < sz1) {   // codebook is the small input (K*D = 32768)
        const float* t = z; z = cb; cb = t;
        int ts = sz0; sz0 = sz1; sz1 = ts;
    }
    int B = sz0 / VQ_D;

    cudaFuncSetAttribute(vq_kernel, cudaFuncAttributeMaxDynamicSharedMemorySize,
                         VQ_SMEM_BYTES);
    int grid = (B + VQ_MT - 1) / VQ_MT;
    vq_kernel<<<grid, VQ_TPB, VQ_SMEM_BYTES>>>(z, cb, (float*)d_out, B);
}

// round 10
// speedup vs baseline: 4.4103x; 1.1216x over previous
#include <cuda_runtime.h>

// VectorQuantize, register-tiled fp32. B x 64 rows vs 512 x 64 codebook.
// R10: thread grid re-shaped for 1-wavefront LDS:
//   tx in [0,8): 8 codes/thread, interleaved {K0+16i+2tx, +1} i=0..3
//     -> each c LDS.128 = 8 unique contiguous 16B = 128B = 1 wavefront
//   ty in [0,64): 4 rows/thread {2ty,2ty+1} and {+128}
//     -> each z LDS.128 = 4 unique contiguous 16B = 64B = 1 wavefront
// Per dp/warp: 6 LDS = 6 wf vs 32 FFMA2/thread -> shared at 37.5% of fma.
// acc 4x8 = 64 regs; total ~110 < 128 cap (no spills, small hoist headroom).
//
// Precision contract (validated R1/R3/R4/R7/R8/R9, rel_err == 0.0): fp32
// throughout, dist = fl(fl(z_sq - 2*dot) + c_sq); dot = single f32x2 chain
// over dp ascending then fl(x+y); z_sq 4-chain stride-4; c_sq sequential
// scalar; argmin strict '<' ascending k in-thread, lexicographic (dist,k)
// across threads -> first-index tie break (jnp.argmin).

#define VQ_K     512
#define VQ_D     64
#define VQ_TPB   512
#define VQ_MT    256        // rows per CTA
#define VQ_RT    4          // rows per thread
#define VQ_KT    8          // codes per thread per sweep
#define VQ_SC    512        // cT2 dp-row stride (ull)
#define VQ_SZ    256        // zT2 dp-row stride (ull)
#define VQ_NIT   8          // k-sweeps (64 codes per sweep)
#define VQ_RED   9          // reduction row stride (8 tx + 1 pad)

typedef unsigned long long ull;

__device__ __forceinline__ ull vq_fma2(ull a, ull b, ull c) {
    ull d;
    asm("fma.rn.f32x2 %0, %1, %2, %3;" : "=l"(d) : "l"(a), "l"(b), "l"(c));
    return d;
}
__device__ __forceinline__ ull vq_add2(ull a, ull b) {
    ull d;
    asm("add.rn.f32x2 %0, %1, %2;" : "=l"(d) : "l"(a), "l"(b));
    return d;
}
__device__ __forceinline__ float2 vq_unpack(ull a) {
    float2 f;
    asm("mov.b64 {%0, %1}, %2;" : "=f"(f.x), "=f"(f.y) : "l"(a));
    return f;
}
__device__ __forceinline__ ull vq_pack(float x, float y) {
    ull d;
    asm("mov.b64 %0, {%1, %2};" : "=l"(d) : "f"(x), "f"(y));
    return d;
}

#define VQ_CT2_ULL (32 * VQ_SC)      // 16384 ull = 131072 B
#define VQ_ZT2_ULL (32 * VQ_SZ)      //  8192 ull =  65536 B
// cT2 + zT2 + csq(512f) + zsq(256f) = 199680 B
#define VQ_SMEM_BYTES ((VQ_CT2_ULL + VQ_ZT2_ULL) * 8 + (VQ_K + VQ_MT) * 4)
// reduction overlay on zT2: 256*9*(4+4) = 18432 B < 65536 B

__global__ void __launch_bounds__(VQ_TPB, 1)
vq_kernel(const float* __restrict__ z, const float* __restrict__ cb,
          float* __restrict__ out, int B) {
    extern __shared__ ull sm[];
    ull*   cT2   = sm;                           // [dp*512 + k]
    ull*   zT2   = sm + VQ_CT2_ULL;              // [dp*256 + r]
    float* s_csq = (float*)(zT2 + VQ_ZT2_ULL);   // [512]
    float* s_zsq = s_csq + VQ_K;                 // [256]
    float* s_rd  = (float*)zT2;                  // overlay [256*9]
    int*   s_rk  = (int*)(s_rd + VQ_MT * VQ_RED);// overlay [256*9]

    const int tid = threadIdx.x;
    const long long base = (long long)blockIdx.x * VQ_MT;
    const int rows_in = (int)((B - base) < VQ_MT ? (B - base) : VQ_MT);

    // ---- stage codebook transposed, k-minor (conflict-free STS) ----
    {
        const float4* cb4 = reinterpret_cast<const float4*>(cb);
        #pragma unroll 4
        for (int i = tid; i < VQ_K * 16; i += VQ_TPB) {
            int k = i & 511, dg = i >> 9;
            float4 v = cb4[k * 16 + dg];
            cT2[(2 * dg)     * VQ_SC + k] = vq_pack(v.x, v.y);
            cT2[(2 * dg + 1) * VQ_SC + k] = vq_pack(v.z, v.w);
        }
    }
    // ---- stage z tile transposed, r-minor (conflict-free STS) ----
    {
        const float4* z4 = reinterpret_cast<const float4*>(z + base * VQ_D);
        #pragma unroll 2
        for (int i = tid; i < VQ_MT * 16; i += VQ_TPB) {
            int r = i & 255, dg = i >> 8;
            float4 v = (r < rows_in) ? z4[r * 16 + dg]
                                     : make_float4(0.f, 0.f, 0.f, 0.f);
            zT2[(2 * dg)     * VQ_SZ + r] = vq_pack(v.x, v.y);
            zT2[(2 * dg + 1) * VQ_SZ + r] = vq_pack(v.z, v.w);
        }
    }
    __syncthreads();

    // ---- c_sq: sequential scalar over d ascending (chain == R1..R9) ----
    {
        int k = tid;   // TPB == 512 == VQ_K
        float s = 0.0f;
        #pragma unroll
        for (int dp = 0; dp < 32; ++dp) {
            float2 c = vq_unpack(cT2[dp * VQ_SC + k]);
            s = __fmaf_rn(c.x, c.x, s);
            s = __fmaf_rn(c.y, c.y, s);
        }
        s_csq[k] = s;
    }
    // ---- z_sq: 4-chain pairwise, stride-4 interleave (chain == R1..R9) ----
    if (tid < VQ_MT) {
        int r = tid;
        ull a0 = 0, a1 = 0, a2 = 0, a3 = 0;
        #pragma unroll
        for (int i = 0; i < 32; i += 4) {
            ull p0 = zT2[(i + 0) * VQ_SZ + r];
            ull p1 = zT2[(i + 1) * VQ_SZ + r];
            ull p2 = zT2[(i + 2) * VQ_SZ + r];
            ull p3 = zT2[(i + 3) * VQ_SZ + r];
            a0 = vq_fma2(p0, p0, a0);
            a1 = vq_fma2(p1, p1, a1);
            a2 = vq_fma2(p2, p2, a2);
            a3 = vq_fma2(p3, p3, a3);
        }
        float2 s = vq_unpack(vq_add2(vq_add2(a0, a1), vq_add2(a2, a3)));
        s_zsq[r] = __fadd_rn(s.x, s.y);
    }
    __syncthreads();

    // ---- main loop: 8 k-sweeps, thread tile 4 rows x 8 codes ----
    const int tx = tid & 7, ty = tid >> 3;       // tx [0,8), ty [0,64)
    const int r0 = 2 * ty;                       // rows r0,r0+1, r0+128,+129

    float best[VQ_RT];
    int   bk[VQ_RT];
    #pragma unroll
    for (int r = 0; r < VQ_RT; ++r) { best[r] = __int_as_float(0x7f800000); bk[r] = 0; }

    #pragma unroll 1
    for (int it = 0; it < VQ_NIT; ++it) {
        const int K0 = it * 64;
        const int kA = K0 + 2 * tx;   // codes kA+16i, kA+16i+1, i=0..3

        ull acc[VQ_RT][VQ_KT];
        #pragma unroll
        for (int r = 0; r < VQ_RT; ++r)
            #pragma unroll
            for (int kk = 0; kk < VQ_KT; ++kk) acc[r][kk] = 0;

        const ull* cp = cT2 + kA;
        const ull* zp = zT2 + r0;

        #pragma unroll 4
        for (int dp = 0; dp < 32; ++dp) {
            // 4 c loads: each 8 unique contiguous 16B across tx lanes = 1 wf
            ulonglong2 c0 = *reinterpret_cast<const ulonglong2*>(cp + dp * VQ_SC);
            ulonglong2 c1 = *reinterpret_cast<const ulonglong2*>(cp + dp * VQ_SC + 16);
            ulonglong2 c2 = *reinterpret_cast<const ulonglong2*>(cp + dp * VQ_SC + 32);
            ulonglong2 c3 = *reinterpret_cast<const ulonglong2*>(cp + dp * VQ_SC + 48);
            ull cf[VQ_KT] = { c0.x, c0.y, c1.x, c1.y, c2.x, c2.y, c3.x, c3.y };

            // 2 z loads: 4 unique contiguous 16B across ty values = 1 wf
            ulonglong2 za = *reinterpret_cast<const ulonglong2*>(zp + dp * VQ_SZ);
            ulonglong2 zb = *reinterpret_cast<const ulonglong2*>(zp + dp * VQ_SZ + 128);
            ull zr[VQ_RT] = { za.x, za.y, zb.x, zb.y };

            #pragma unroll
            for (int r = 0; r < VQ_RT; ++r)
                #pragma unroll
                for (int kk = 0; kk < VQ_KT; ++kk)
                    acc[r][kk] = vq_fma2(zr[r], cf[kk], acc[r][kk]);
        }

        // per-sweep epilogue: dist + argmin
        // thread codes ascending: kA+16i+{0,1} (2tx+1 < 16 -> strictly ascending)
        #pragma unroll
        for (int j = 0; j < 2; ++j) {
            #pragma unroll
            for (int h = 0; h < 2; ++h) {
                const int r = 2 * j + h;
                const float zq = s_zsq[r0 + 128 * j + h];
                #pragma unroll
                for (int kk = 0; kk < VQ_KT; ++kk) {
                    const int kc = kA + 16 * (kk >> 1) + (kk & 1);
                    float2 f = vq_unpack(acc[r][kk]);
                    float dot  = __fadd_rn(f.x, f.y);
                    float t    = __fsub_rn(zq, __fmul_rn(2.0f, dot));
                    float dist = __fadd_rn(t, s_csq[kc]);
                    bool p = dist < best[r];
                    best[r] = p ? dist : best[r];
                    bk[r]   = p ? kc : bk[r];
                }
            }
        }
    }

    // ---- cross-thread argmin reduction (overlay on dead zT2) ----
    __syncthreads();   // all main-loop zT2 reads complete
    #pragma unroll
    for (int j = 0; j < 2; ++j)
        #pragma unroll
        for (int h = 0; h < 2; ++h) {
            const int row = r0 + 128 * j + h;
            s_rd[row * VQ_RED + tx] = best[2 * j + h];
            s_rk[row * VQ_RED + tx] = bk[2 * j + h];
        }
    __syncthreads();
    if (tid < VQ_MT) {
        int r = tid;
        float bd = s_rd[r * VQ_RED + 0];
        int   bi = s_rk[r * VQ_RED + 0];
        #pragma unroll
        for (int t = 1; t < 8; ++t) {
            float d = s_rd[r * VQ_RED + t];
            int   i = s_rk[r * VQ_RED + t];
            bool p = (d < bd) || (d == bd && i < bi);
            bd = p ? d : bd;
            bi = p ? i : bi;
        }
        s_rk[r * VQ_RED] = bi;
    }
    __syncthreads();

    // ---- outputs: z and cb from GLOBAL (coalesced; L2-resident) ----
    {
        const float4* cb4 = reinterpret_cast<const float4*>(cb);
        const float4* z4  = reinterpret_cast<const float4*>(z + base * VQ_D);
        float4* o1 = reinterpret_cast<float4*>(out) + base * 16;
        float4* o2 = reinterpret_cast<float4*>(out) + (long long)B * 16 + base * 16;
        #pragma unroll 2
        for (int c = tid; c < VQ_MT * 16; c += VQ_TPB) {
            int r = c >> 4, dg = c & 15;
            if (r >= rows_in) break;
            int kbest = s_rk[r * VQ_RED];
            float4 qv = cb4[kbest * 16 + dg];
            float4 zv = z4[c];
            float4 w;
            w.x = __fadd_rn(zv.x, __fsub_rn(qv.x, zv.x));
            w.y = __fadd_rn(zv.y, __fsub_rn(qv.y, zv.y));
            w.z = __fadd_rn(zv.z, __fsub_rn(qv.z, zv.z));
            w.w = __fadd_rn(zv.w, __fsub_rn(qv.w, zv.w));
            o1[c] = w;
            o2[c] = qv;
        }
    }
}

extern "C" void kernel_launch(void* const* d_in, const int* in_sizes, int n_in,
                              void* d_out, int out_size) {
    const float* z  = (const float*)d_in[0];
    const float* cb = (const float*)d_in[1];
    int sz0 = in_sizes[0];
    int sz1 = (n_in > 1) ? in_sizes[1] : 0;
    if (sz0 < sz1) {   // codebook is the small input (K*D = 32768)
        const float* t = z; z = cb; cb = t;
        int ts = sz0; sz0 = sz1; sz1 = ts;
    }
    int B = sz0 / VQ_D;

    cudaFuncSetAttribute(vq_kernel, cudaFuncAttributeMaxDynamicSharedMemorySize,
                         VQ_SMEM_BYTES);
    int grid = (B + VQ_MT - 1) / VQ_MT;
    vq_kernel<<<grid, VQ_TPB, VQ_SMEM_BYTES>>>(z, cb, (float*)d_out, B);
}

// round 11
// speedup vs baseline: 4.5626x; 1.0345x over previous
#include <cuda_runtime.h>

// VectorQuantize, register-tiled fp32. B x 64 rows vs 512 x 64 codebook.
// R11: 256 threads/CTA (255-reg budget), balanced 8x8 thread tile.
// Wavefront model (validated on R10): LDS.128 = 4 quarter-warp wavefronts;
// wf/warp/dp = thread_bytes/4 = 2(r+k). Balance rk >= 4(r+k) -> 8x8.
// Per dp: shared 256 wf-cyc/SM == fma 256 cyc/SMSP -> both pipes saturate.
//
// Precision contract (validated R1/R3/R4/R7-R10, rel_err == 0.0): fp32
// throughout, dist = fl(fl(z_sq - 2*dot) + c_sq); dot = single f32x2 chain
// over dp ascending then fl(x+y); z_sq 4-chain stride-4; c_sq sequential
// scalar; argmin strict '<' ascending k in-thread, lexicographic (dist,k)
// across threads -> first-index tie break (jnp.argmin).

#define VQ_K     512
#define VQ_D     64
#define VQ_TPB   256
#define VQ_MT    256        // rows per CTA
#define VQ_RT    8          // rows per thread (4 pairs strided by 64)
#define VQ_KT    8          // codes per thread per sweep
#define VQ_SC    512        // cT2 dp-row stride (ull)
#define VQ_SZ    256        // zT2 dp-row stride (ull)
#define VQ_NIT   8          // k-sweeps (64 codes per sweep)
#define VQ_RED   9          // reduction row stride (8 tx + 1 pad)

typedef unsigned long long ull;

__device__ __forceinline__ ull vq_fma2(ull a, ull b, ull c) {
    ull d;
    asm("fma.rn.f32x2 %0, %1, %2, %3;" : "=l"(d) : "l"(a), "l"(b), "l"(c));
    return d;
}
__device__ __forceinline__ ull vq_add2(ull a, ull b) {
    ull d;
    asm("add.rn.f32x2 %0, %1, %2;" : "=l"(d) : "l"(a), "l"(b));
    return d;
}
__device__ __forceinline__ float2 vq_unpack(ull a) {
    float2 f;
    asm("mov.b64 {%0, %1}, %2;" : "=f"(f.x), "=f"(f.y) : "l"(a));
    return f;
}
__device__ __forceinline__ ull vq_pack(float x, float y) {
    ull d;
    asm("mov.b64 %0, {%1, %2};" : "=l"(d) : "f"(x), "f"(y));
    return d;
}

#define VQ_CT2_ULL (32 * VQ_SC)      // 16384 ull = 131072 B
#define VQ_ZT2_ULL (32 * VQ_SZ)      //  8192 ull =  65536 B
#define VQ_SMEM_BYTES ((VQ_CT2_ULL + VQ_ZT2_ULL) * 8 + (VQ_K + VQ_MT) * 4)
// reduction overlay on zT2: 256*9*(4+4) = 18432 B < 65536 B

__global__ void __launch_bounds__(VQ_TPB, 1)
vq_kernel(const float* __restrict__ z, const float* __restrict__ cb,
          float* __restrict__ out, int B) {
    extern __shared__ ull sm[];
    ull*   cT2   = sm;                           // [dp*512 + k]
    ull*   zT2   = sm + VQ_CT2_ULL;              // [dp*256 + r]
    float* s_csq = (float*)(zT2 + VQ_ZT2_ULL);   // [512]
    float* s_zsq = s_csq + VQ_K;                 // [256]
    float* s_rd  = (float*)zT2;                  // overlay [256*9]
    int*   s_rk  = (int*)(s_rd + VQ_MT * VQ_RED);// overlay [256*9]

    const int tid = threadIdx.x;
    const long long base = (long long)blockIdx.x * VQ_MT;
    const int rows_in = (int)((B - base) < VQ_MT ? (B - base) : VQ_MT);

    // ---- stage codebook transposed, k-minor (conflict-free STS) ----
    {
        const float4* cb4 = reinterpret_cast<const float4*>(cb);
        #pragma unroll 4
        for (int i = tid; i < VQ_K * 16; i += VQ_TPB) {
            int k = i & 511, dg = i >> 9;
            float4 v = cb4[k * 16 + dg];
            cT2[(2 * dg)     * VQ_SC + k] = vq_pack(v.x, v.y);
            cT2[(2 * dg + 1) * VQ_SC + k] = vq_pack(v.z, v.w);
        }
    }
    // ---- stage z tile transposed, r-minor (conflict-free STS) ----
    {
        const float4* z4 = reinterpret_cast<const float4*>(z + base * VQ_D);
        #pragma unroll 4
        for (int i = tid; i < VQ_MT * 16; i += VQ_TPB) {
            int r = i & 255, dg = i >> 8;
            float4 v = (r < rows_in) ? z4[r * 16 + dg]
                                     : make_float4(0.f, 0.f, 0.f, 0.f);
            zT2[(2 * dg)     * VQ_SZ + r] = vq_pack(v.x, v.y);
            zT2[(2 * dg + 1) * VQ_SZ + r] = vq_pack(v.z, v.w);
        }
    }
    __syncthreads();

    // ---- c_sq: sequential scalar over d ascending (chain == R1..R10) ----
    #pragma unroll
    for (int k = tid; k < VQ_K; k += VQ_TPB) {
        float s = 0.0f;
        #pragma unroll
        for (int dp = 0; dp < 32; ++dp) {
            float2 c = vq_unpack(cT2[dp * VQ_SC + k]);
            s = __fmaf_rn(c.x, c.x, s);
            s = __fmaf_rn(c.y, c.y, s);
        }
        s_csq[k] = s;
    }
    // ---- z_sq: 4-chain pairwise, stride-4 interleave (chain == R1..R10) ----
    {
        int r = tid;   // TPB == 256 == VQ_MT
        ull a0 = 0, a1 = 0, a2 = 0, a3 = 0;
        #pragma unroll
        for (int i = 0; i < 32; i += 4) {
            ull p0 = zT2[(i + 0) * VQ_SZ + r];
            ull p1 = zT2[(i + 1) * VQ_SZ + r];
            ull p2 = zT2[(i + 2) * VQ_SZ + r];
            ull p3 = zT2[(i + 3) * VQ_SZ + r];
            a0 = vq_fma2(p0, p0, a0);
            a1 = vq_fma2(p1, p1, a1);
            a2 = vq_fma2(p2, p2, a2);
            a3 = vq_fma2(p3, p3, a3);
        }
        float2 s = vq_unpack(vq_add2(vq_add2(a0, a1), vq_add2(a2, a3)));
        s_zsq[r] = __fadd_rn(s.x, s.y);
    }
    __syncthreads();

    // ---- main loop: 8 k-sweeps, thread tile 8 rows x 8 codes ----
    const int tx = tid & 7, ty = tid >> 3;       // tx [0,8), ty [0,32)
    const int r0 = 2 * ty;                       // row pairs r0+{0,1}+64p

    float best[VQ_RT];
    int   bk[VQ_RT];
    #pragma unroll
    for (int r = 0; r < VQ_RT; ++r) { best[r] = __int_as_float(0x7f800000); bk[r] = 0; }

    #pragma unroll 1
    for (int it = 0; it < VQ_NIT; ++it) {
        const int K0 = it * 64;
        const int kA = K0 + 2 * tx;   // codes kA+16i, kA+16i+1, i=0..3

        ull acc[VQ_RT][VQ_KT];
        #pragma unroll
        for (int r = 0; r < VQ_RT; ++r)
            #pragma unroll
            for (int kk = 0; kk < VQ_KT; ++kk) acc[r][kk] = 0;

        const ull* cp = cT2 + kA;
        const ull* zp = zT2 + r0;

        #pragma unroll 4
        for (int dp = 0; dp < 32; ++dp) {
            ulonglong2 c0 = *reinterpret_cast<const ulonglong2*>(cp + dp * VQ_SC);
            ulonglong2 c1 = *reinterpret_cast<const ulonglong2*>(cp + dp * VQ_SC + 16);
            ulonglong2 c2 = *reinterpret_cast<const ulonglong2*>(cp + dp * VQ_SC + 32);
            ulonglong2 c3 = *reinterpret_cast<const ulonglong2*>(cp + dp * VQ_SC + 48);
            ull cf[VQ_KT] = { c0.x, c0.y, c1.x, c1.y, c2.x, c2.y, c3.x, c3.y };

            ulonglong2 za = *reinterpret_cast<const ulonglong2*>(zp + dp * VQ_SZ);
            ulonglong2 zb = *reinterpret_cast<const ulonglong2*>(zp + dp * VQ_SZ + 64);
            ulonglong2 zc = *reinterpret_cast<const ulonglong2*>(zp + dp * VQ_SZ + 128);
            ulonglong2 zd = *reinterpret_cast<const ulonglong2*>(zp + dp * VQ_SZ + 192);
            ull zr[VQ_RT] = { za.x, za.y, zb.x, zb.y, zc.x, zc.y, zd.x, zd.y };

            #pragma unroll
            for (int r = 0; r < VQ_RT; ++r)
                #pragma unroll
                for (int kk = 0; kk < VQ_KT; ++kk)
                    acc[r][kk] = vq_fma2(zr[r], cf[kk], acc[r][kk]);
        }

        // per-sweep epilogue: dist + argmin
        // thread codes ascending: kA+16i+{0,1} (2tx+1 < 16 -> ascending in kk)
        #pragma unroll
        for (int p = 0; p < 4; ++p) {
            #pragma unroll
            for (int h = 0; h < 2; ++h) {
                const int r = 2 * p + h;
                const float zq = s_zsq[r0 + 64 * p + h];
                #pragma unroll
                for (int kk = 0; kk < VQ_KT; ++kk) {
                    const int kc = kA + 16 * (kk >> 1) + (kk & 1);
                    float2 f = vq_unpack(acc[r][kk]);
                    float dot  = __fadd_rn(f.x, f.y);
                    float t    = __fsub_rn(zq, __fmul_rn(2.0f, dot));
                    float dist = __fadd_rn(t, s_csq[kc]);
                    bool pr = dist < best[r];
                    best[r] = pr ? dist : best[r];
                    bk[r]   = pr ? kc : bk[r];
                }
            }
        }
    }

    // ---- cross-thread argmin reduction (overlay on dead zT2) ----
    __syncthreads();   // all main-loop zT2 reads complete
    #pragma unroll
    for (int p = 0; p < 4; ++p)
        #pragma unroll
        for (int h = 0; h < 2; ++h) {
            const int row = r0 + 64 * p + h;
            s_rd[row * VQ_RED + tx] = best[2 * p + h];
            s_rk[row * VQ_RED + tx] = bk[2 * p + h];
        }
    __syncthreads();
    {
        int r = tid;   // TPB == VQ_MT
        float bd = s_rd[r * VQ_RED + 0];
        int   bi = s_rk[r * VQ_RED + 0];
        #pragma unroll
        for (int t = 1; t < 8; ++t) {
            float d = s_rd[r * VQ_RED + t];
            int   i = s_rk[r * VQ_RED + t];
            bool p = (d < bd) || (d == bd && i < bi);
            bd = p ? d : bd;
            bi = p ? i : bi;
        }
        s_rk[r * VQ_RED] = bi;
    }
    __syncthreads();

    // ---- outputs: z and cb from GLOBAL (coalesced; L2-resident) ----
    {
        const float4* cb4 = reinterpret_cast<const float4*>(cb);
        const float4* z4  = reinterpret_cast<const float4*>(z + base * VQ_D);
        float4* o1 = reinterpret_cast<float4*>(out) + base * 16;
        float4* o2 = reinterpret_cast<float4*>(out) + (long long)B * 16 + base * 16;
        #pragma unroll 4
        for (int c = tid; c < VQ_MT * 16; c += VQ_TPB) {
            int r = c >> 4, dg = c & 15;
            if (r >= rows_in) break;
            int kbest = s_rk[r * VQ_RED];
            float4 qv = cb4[kbest * 16 + dg];
            float4 zv = z4[c];
            float4 w;
            w.x = __fadd_rn(zv.x, __fsub_rn(qv.x, zv.x));
            w.y = __fadd_rn(zv.y, __fsub_rn(qv.y, zv.y));
            w.z = __fadd_rn(zv.z, __fsub_rn(qv.z, zv.z));
            w.w = __fadd_rn(zv.w, __fsub_rn(qv.w, zv.w));
            o1[c] = w;
            o2[c] = qv;
        }
    }
}

extern "C" void kernel_launch(void* const* d_in, const int* in_sizes, int n_in,
                              void* d_out, int out_size) {
    const float* z  = (const float*)d_in[0];
    const float* cb = (const float*)d_in[1];
    int sz0 = in_sizes[0];
    int sz1 = (n_in > 1) ? in_sizes[1] : 0;
    if (sz0 < sz1) {   // codebook is the small input (K*D = 32768)
        const float* t = z; z = cb; cb = t;
        int ts = sz0; sz0 = sz1; sz1 = ts;
    }
    int B = sz0 / VQ_D;

    cudaFuncSetAttribute(vq_kernel, cudaFuncAttributeMaxDynamicSharedMemorySize,
                         VQ_SMEM_BYTES);
    int grid = (B + VQ_MT - 1) / VQ_MT;
    vq_kernel<<<grid, VQ_TPB, VQ_SMEM_BYTES>>>(z, cb, (float*)d_out, B);
}